// round 4
// baseline (speedup 1.0000x reference)
#include <cuda_runtime.h>
#include <cstdint>

typedef unsigned long long ull;

#define H     51
#define G4    (4*H)       // 204 real gates
#define GP    256         // padded gate count
#define GROW  260         // g row stride (floats) -> conflict-free gate reads
#define HROW  108         // plain h row stride: 104 used (h1[51],h2[51],pad2) +4
#define BB    8           // batch per block
#define TSEQ  512
#define FUT   64
#define TTOT  (TSEQ + FUT)
#define NT    384         // 12 warps: 2 j-slices x 6 k-splits
#define NKS   6           // split-K factor

// ---- smem layout (float offsets) ----
#define OFF_W1T  0
#define SZ_W1T   (52*GP)                  // 13312
#define OFF_W2T  (OFF_W1T + SZ_W1T)
#define SZ_W2T   (104*GP)                 // 26624
#define OFF_WX   (OFF_W2T + SZ_W2T)       // 39936
#define OFF_B1   (OFF_WX + GP)
#define OFF_B2   (OFF_B1 + GP)
#define OFF_WL   (OFF_B2 + GP)
#define OFF_HD   (OFF_WL + 64)            // 40768
#define SZ_HD    (BB*HROW)                // 864
#define OFF_G    (OFF_HD + SZ_HD)         // 41632
#define SZ_G     (BB*GROW)                // 2080 per split buffer
#define OFF_OUT  (OFF_G + NKS*SZ_G)       // 54112
#define OFF_BL   (OFF_OUT + 8)
#define SMEM_FLOATS (OFF_BL + 4)          // 54124 -> 216496 B
#define SMEM_BYTES  (SMEM_FLOATS * 4)

__device__ __forceinline__ ull ffma2(ull a, ull b, ull c) {
    ull d;
    asm("fma.rn.f32x2 %0, %1, %2, %3;" : "=l"(d) : "l"(a), "l"(b), "l"(c));
    return d;
}

__device__ __forceinline__ ull dup2(float v) {
    ull r;
    unsigned u = __float_as_uint(v);
    asm("mov.b64 %0, {%1, %2};" : "=l"(r) : "r"(u), "r"(u));
    return r;
}

__device__ __forceinline__ float fsig(float x) {
    float e = __expf(-x);
    return __fdividef(1.0f, 1.0f + e);
}

__device__ __forceinline__ float ftanh_acc(float x) {
    float a = fabsf(x);
    float e = __expf(-2.0f * a);           // <= 1, no overflow
    float r = __fdividef(1.0f - e, 1.0f + e);
    return copysignf(r, x);
}

// Partial matvec over NQ k-quads (4 k each) for 4 gates/lane, 8 batches.
// Per quad: 4 weight LDS.128 (16 wf) + 8 broadcast-h LDS.128 (8 wf) feed
// 64 FFMA2 => 0.375 wf/FFMA2. Duplication to f32x2 is done via ALU movs.
template<int NQ>
__device__ __forceinline__ void matvec(const float* __restrict__ WT,
                                       const float* __restrict__ hd,
                                       ull acc0[8], ull acc1[8], int j0)
{
    #pragma unroll
    for (int q = 0; q < NQ; ++q) {
        ulonglong2 w0 = *reinterpret_cast<const ulonglong2*>(WT + (4*q  )*GP + j0);
        ulonglong2 w1 = *reinterpret_cast<const ulonglong2*>(WT + (4*q+1)*GP + j0);
        ulonglong2 w2 = *reinterpret_cast<const ulonglong2*>(WT + (4*q+2)*GP + j0);
        ulonglong2 w3 = *reinterpret_cast<const ulonglong2*>(WT + (4*q+3)*GP + j0);
        #pragma unroll
        for (int b = 0; b < 8; ++b) {
            float4 hv = *reinterpret_cast<const float4*>(hd + b*HROW + 4*q);
            ull d0 = dup2(hv.x), d1 = dup2(hv.y), d2 = dup2(hv.z), d3 = dup2(hv.w);
            acc0[b] = ffma2(w0.x, d0, acc0[b]);
            acc1[b] = ffma2(w0.y, d0, acc1[b]);
            acc0[b] = ffma2(w1.x, d1, acc0[b]);
            acc1[b] = ffma2(w1.y, d1, acc1[b]);
            acc0[b] = ffma2(w2.x, d2, acc0[b]);
            acc1[b] = ffma2(w2.y, d2, acc1[b]);
            acc0[b] = ffma2(w3.x, d3, acc0[b]);
            acc1[b] = ffma2(w3.y, d3, acc1[b]);
        }
    }
}

__device__ __forceinline__ void store_acc(float* __restrict__ gout,
                                          ull acc0[8], ull acc1[8], int j0)
{
    #pragma unroll
    for (int b = 0; b < 8; ++b)
        *reinterpret_cast<ulonglong2*>(gout + b*GROW + j0) =
            make_ulonglong2(acc0[b], acc1[b]);
}

// gate nonlinearity: 408 (b,h) tasks over 384 threads (2 iters, 2nd sparse);
// sums the 6 split-K partial buffers; c state lives in registers.
__device__ __forceinline__ void gates(const float* __restrict__ g,
                                      float* __restrict__ hd,
                                      float creg[2], int hoff, int tid)
{
    #pragma unroll
    for (int i = 0; i < 2; ++i) {
        int tt = tid + i*NT;
        if (tt < BB*H) {
            int b = tt & 7, h = tt >> 3;
            int base = b*GROW + h;
            float gi = 0.f, gf = 0.f, gg = 0.f, go = 0.f;
            #pragma unroll
            for (int s = 0; s < NKS; ++s) {
                const float* gr = g + s*SZ_G + base;
                gi += gr[0];
                gf += gr[H];
                gg += gr[2*H];
                go += gr[3*H];
            }
            float c  = fsig(gf)*creg[i] + fsig(gi)*ftanh_acc(gg);
            float hn = fsig(go)*ftanh_acc(c);
            creg[i] = c;
            hd[b*HROW + hoff + h] = hn;      // plain store (no duplication)
        }
    }
}

__global__ void __launch_bounds__(NT, 1)
lstm_seq_kernel(const float* __restrict__ input,
                const float* __restrict__ Wih1, const float* __restrict__ Whh1,
                const float* __restrict__ bih1, const float* __restrict__ bhh1,
                const float* __restrict__ Wih2, const float* __restrict__ Whh2,
                const float* __restrict__ bih2, const float* __restrict__ bhh2,
                const float* __restrict__ Wl,   const float* __restrict__ bl,
                float* __restrict__ out)
{
    extern __shared__ __align__(16) float sm[];
    const int tid = threadIdx.x;
    const int b0  = blockIdx.x * BB;

    // ---------- one-time prep: stage transposed/padded weights ----------
    for (int idx = tid; idx < SZ_W1T; idx += NT) {
        int k = idx >> 8, j = idx & 255;
        sm[OFF_W1T + idx] = (j < G4 && k < H) ? Whh1[j*H + k] : 0.0f;
    }
    for (int idx = tid; idx < SZ_W2T; idx += NT) {
        int k = idx >> 8, j = idx & 255;
        float v = 0.0f;
        if (j < G4) {
            if (k < H)        v = Wih2[j*H + k];
            else if (k < 2*H) v = Whh2[j*H + (k - H)];
        }
        sm[OFF_W2T + idx] = v;
    }
    for (int j = tid; j < GP; j += NT) {
        bool r = (j < G4);
        sm[OFF_WX + j] = r ? Wih1[j] : 0.0f;
        sm[OFF_B1 + j] = r ? (bih1[j] + bhh1[j]) : 0.0f;
        sm[OFF_B2 + j] = r ? (bih2[j] + bhh2[j]) : 0.0f;
    }
    if (tid < 64) sm[OFF_WL + tid] = (tid < H) ? Wl[tid] : 0.0f;
    for (int idx = tid; idx < SZ_HD; idx += NT) sm[OFF_HD + idx] = 0.0f;
    for (int idx = tid; idx < NKS*SZ_G; idx += NT) sm[OFF_G + idx] = 0.0f;
    if (tid < 8)   sm[OFF_OUT + tid] = 0.0f;
    if (tid == 0)  sm[OFF_BL] = bl[0];
    __syncthreads();

    float c1r[2] = {0.f, 0.f};
    float c2r[2] = {0.f, 0.f};

    const int wid  = tid >> 5, lane = tid & 31;
    const int js   = wid & 1;                // j-slice (2 x 128 gates)
    const int kh   = wid >> 1;               // k-split group (0..5)
    const int j0   = js*128 + lane*4;        // 4 consecutive gates per lane
    float* gout = sm + OFF_G + kh*SZ_G;

    // layer1: 13 quads split {3,2,2,2,2,2}; layer2: 26 quads {5,5,4,4,4,4}
    const int s1q = (kh == 0) ? 0 : 3 + 2*(kh - 1);
    const int s2q = (kh < 2) ? 5*kh : 10 + 4*(kh - 2);
    const int n1q = (kh == 0) ? 3 : 2;
    const float* W1T = sm + OFF_W1T + s1q*4*GP;
    const float* W2T = sm + OFF_W2T + s2q*4*GP;
    const float* hd1 = sm + OFF_HD + s1q*4;
    const float* hd2 = sm + OFF_HD + s2q*4;
    float* hd = sm + OFF_HD;

    // x prefetch (kh==0 warps only): lane b<8 holds input[(b0+b)*T + t]
    float xcur = 0.f;
    if (kh == 0 && lane < 8) xcur = input[(b0 + lane)*TSEQ];

    for (int t = 0; t < TTOT; ++t) {
        // ---- matvec layer 1 (partial over this warp's k-quads) ----
        {
            ull acc0[8], acc1[8];
            if (kh == 0) {
                ulonglong2 bv  = *reinterpret_cast<const ulonglong2*>(sm + OFF_B1 + j0);
                ulonglong2 wxv = *reinterpret_cast<const ulonglong2*>(sm + OFF_WX + j0);
                #pragma unroll
                for (int b = 0; b < 8; ++b) {
                    float x = (t < TSEQ) ? __shfl_sync(0xffffffffu, xcur, b)
                                         : sm[OFF_OUT + b];
                    ull xx = dup2(x);
                    acc0[b] = ffma2(wxv.x, xx, bv.x);
                    acc1[b] = ffma2(wxv.y, xx, bv.y);
                }
                // prefetch next step's x (hidden behind the full step)
                if (t + 1 < TSEQ && lane < 8)
                    xcur = input[(b0 + lane)*TSEQ + (t + 1)];
            } else {
                #pragma unroll
                for (int b = 0; b < 8; ++b) { acc0[b] = 0ull; acc1[b] = 0ull; }
            }
            if (kh == 0) matvec<3>(W1T, hd1, acc0, acc1, j0);
            else         matvec<2>(W1T, hd1, acc0, acc1, j0);
            store_acc(gout, acc0, acc1, j0);
        }
        __syncthreads();

        gates(sm + OFF_G, hd, c1r, 0, tid);     // h1 -> hd[b][0..51)
        __syncthreads();

        // ---- matvec layer 2 (partial over this warp's k-quads) ----
        {
            ull acc0[8], acc1[8];
            if (kh == 0) {
                ulonglong2 bv = *reinterpret_cast<const ulonglong2*>(sm + OFF_B2 + j0);
                #pragma unroll
                for (int b = 0; b < 8; ++b) { acc0[b] = bv.x; acc1[b] = bv.y; }
            } else {
                #pragma unroll
                for (int b = 0; b < 8; ++b) { acc0[b] = 0ull; acc1[b] = 0ull; }
            }
            if (kh < 2) matvec<5>(W2T, hd2, acc0, acc1, j0);
            else        matvec<4>(W2T, hd2, acc0, acc1, j0);
            store_acc(gout, acc0, acc1, j0);
        }
        __syncthreads();

        gates(sm + OFF_G, hd, c2r, H, tid);     // h2 -> hd[b][51..102)
        __syncthreads();

        // ---- output: out[b] = h2 . Wl + bl ; warps 0-7 handle batch=wid ----
        if (wid < 8) {
            const float* h2p = hd + wid*HROW + H;
            float p = h2p[lane] * sm[OFF_WL + lane];
            if (lane + 32 < H)
                p += h2p[lane + 32] * sm[OFF_WL + lane + 32];
            #pragma unroll
            for (int o = 16; o > 0; o >>= 1)
                p += __shfl_xor_sync(0xffffffffu, p, o);
            if (lane == 0) {
                float ov = p + sm[OFF_BL];
                out[(b0 + wid)*TTOT + t] = ov;
                sm[OFF_OUT + wid] = ov;   // feeds future-phase x
            }
        }
        __syncthreads();
    }
}

extern "C" void kernel_launch(void* const* d_in, const int* in_sizes, int n_in,
                              void* d_out, int out_size)
{
    (void)n_in; (void)out_size;
    cudaFuncSetAttribute(lstm_seq_kernel,
                         cudaFuncAttributeMaxDynamicSharedMemorySize, SMEM_BYTES);
    int nblocks = in_sizes[0] / (TSEQ * BB);   // B / 8 = 128
    lstm_seq_kernel<<<nblocks, NT, SMEM_BYTES>>>(
        (const float*)d_in[0],  (const float*)d_in[1], (const float*)d_in[2],
        (const float*)d_in[3],  (const float*)d_in[4], (const float*)d_in[5],
        (const float*)d_in[6],  (const float*)d_in[7], (const float*)d_in[8],
        (const float*)d_in[9],  (const float*)d_in[10],
        (float*)d_out);
}

// round 5
// speedup vs baseline: 1.0220x; 1.0220x over previous
#include <cuda_runtime.h>
#include <cstdint>

typedef unsigned long long ull;

#define H     51
#define G4    (4*H)       // 204 real gates
#define GP    256         // padded gate count (interleaved layout: col = 4h+g)
#define GROW  260         // g row stride (floats)
#define HROW  212         // dup h row stride: 2*104=208 -> 212
#define BB    8           // batch per block
#define TSEQ  512
#define FUT   64
#define TTOT  (TSEQ + FUT)
#define NT    256         // 8 warps: 2 j-slices x 4 k-splits
#define NKS   4           // split-K factor

// ---- smem layout (float offsets) ----
#define OFF_W1T  0
#define SZ_W1T   (52*GP)                  // 13312
#define OFF_W2T  (OFF_W1T + SZ_W1T)
#define SZ_W2T   (104*GP)                 // 26624
#define OFF_WX   (OFF_W2T + SZ_W2T)       // 39936
#define OFF_B1   (OFF_WX + GP)
#define OFF_B2   (OFF_B1 + GP)
#define OFF_WL   (OFF_B2 + GP)
#define OFF_HD   (OFF_WL + 64)
#define SZ_HD    (BB*HROW)                // 1696
#define OFF_G    (OFF_HD + SZ_HD)
#define SZ_G     (BB*GROW)                // 2080 per split buffer
#define OFF_OUT  (OFF_G + NKS*SZ_G)
#define OFF_BL   (OFF_OUT + 8)
#define SMEM_FLOATS (OFF_BL + 4)          // ~50796 -> 203184 B
#define SMEM_BYTES  (SMEM_FLOATS * 4)

__device__ __forceinline__ ull ffma2(ull a, ull b, ull c) {
    ull d;
    asm("fma.rn.f32x2 %0, %1, %2, %3;" : "=l"(d) : "l"(a), "l"(b), "l"(c));
    return d;
}

__device__ __forceinline__ ull dup2(float v) {
    ull r;
    unsigned u = __float_as_uint(v);
    asm("mov.b64 %0, {%1, %2};" : "=l"(r) : "r"(u), "r"(u));
    return r;
}

__device__ __forceinline__ float fsig(float x) {
    float e = __expf(-x);
    return __fdividef(1.0f, 1.0f + e);
}

__device__ __forceinline__ float ftanh_acc(float x) {
    float a = fabsf(x);
    float e = __expf(-2.0f * a);           // <= 1, no overflow
    float r = __fdividef(1.0f - e, 1.0f + e);
    return copysignf(r, x);
}

// Partial matvec over NPAIR k-pairs, 4 gate-cols per lane, 8 batches.
// Per pair: 2 weight LDS.128 + 8 dup-h broadcast LDS.128 -> 32 FFMA2
// (1.31 instr / FFMA2, 0.5 wavefront / FFMA2).
template<int NPAIR>
__device__ __forceinline__ void matvec(const float* __restrict__ WT,
                                       const float* __restrict__ hd,
                                       ull acc0[8], ull acc1[8], int j0)
{
    #pragma unroll
    for (int kp = 0; kp < NPAIR; ++kp) {
        ulonglong2 w0 = *reinterpret_cast<const ulonglong2*>(WT + (2*kp  )*GP + j0);
        ulonglong2 w1 = *reinterpret_cast<const ulonglong2*>(WT + (2*kp+1)*GP + j0);
        #pragma unroll
        for (int b = 0; b < 8; ++b) {
            // (h[2kp],h[2kp], h[2kp+1],h[2kp+1]) — pre-duplicated, broadcast
            ulonglong2 hv = *reinterpret_cast<const ulonglong2*>(hd + b*HROW + 4*kp);
            acc0[b] = ffma2(w0.x, hv.x, acc0[b]);
            acc1[b] = ffma2(w0.y, hv.x, acc1[b]);
            acc0[b] = ffma2(w1.x, hv.y, acc0[b]);
            acc1[b] = ffma2(w1.y, hv.y, acc1[b]);
        }
    }
}

__device__ __forceinline__ void store_acc(float* __restrict__ gout,
                                          ull acc0[8], ull acc1[8], int j0)
{
    #pragma unroll
    for (int b = 0; b < 8; ++b)
        *reinterpret_cast<ulonglong2*>(gout + b*GROW + j0) =
            make_ulonglong2(acc0[b], acc1[b]);
}

// gate nonlinearity: 408 (b,h) tasks; interleaved layout -> one LDS.128 per
// split buffer gives (i,f,g,o) of unit h; 4-way split-K reduction folded in.
__device__ __forceinline__ void gates(const float* __restrict__ g,
                                      float* __restrict__ hd,
                                      float creg[2], int hoff, int tid)
{
    #pragma unroll
    for (int i = 0; i < 2; ++i) {
        int tt = tid + i*NT;
        if (tt < BB*H) {
            int b = tt & 7, h = tt >> 3;
            const float* gp = g + b*GROW + 4*h;
            float4 v0 = *reinterpret_cast<const float4*>(gp);
            float4 v1 = *reinterpret_cast<const float4*>(gp + SZ_G);
            float4 v2 = *reinterpret_cast<const float4*>(gp + 2*SZ_G);
            float4 v3 = *reinterpret_cast<const float4*>(gp + 3*SZ_G);
            float gi = (v0.x + v1.x) + (v2.x + v3.x);
            float gf = (v0.y + v1.y) + (v2.y + v3.y);
            float gg = (v0.z + v1.z) + (v2.z + v3.z);
            float go = (v0.w + v1.w) + (v2.w + v3.w);
            float c  = fsig(gf)*creg[i] + fsig(gi)*ftanh_acc(gg);
            float hn = fsig(go)*ftanh_acc(c);
            creg[i] = c;
            *reinterpret_cast<float2*>(hd + b*HROW + 2*(hoff + h)) = make_float2(hn, hn);
        }
    }
}

__global__ void __launch_bounds__(NT, 1)
lstm_seq_kernel(const float* __restrict__ input,
                const float* __restrict__ Wih1, const float* __restrict__ Whh1,
                const float* __restrict__ bih1, const float* __restrict__ bhh1,
                const float* __restrict__ Wih2, const float* __restrict__ Whh2,
                const float* __restrict__ bih2, const float* __restrict__ bhh2,
                const float* __restrict__ Wl,   const float* __restrict__ bl,
                float* __restrict__ out)
{
    extern __shared__ __align__(16) float sm[];
    const int tid = threadIdx.x;
    const int b0  = blockIdx.x * BB;

    // ------- one-time prep: stage transposed + gate-interleaved weights -------
    // interleaved col j' = 4h+g  <->  original row = g*H + h
    for (int idx = tid; idx < SZ_W1T; idx += NT) {
        int k = idx >> 8, j = idx & 255;
        float v = 0.0f;
        if (j < G4 && k < H) {
            int row = (j & 3)*H + (j >> 2);
            v = Whh1[row*H + k];
        }
        sm[OFF_W1T + idx] = v;
    }
    for (int idx = tid; idx < SZ_W2T; idx += NT) {
        int k = idx >> 8, j = idx & 255;
        float v = 0.0f;
        if (j < G4) {
            int row = (j & 3)*H + (j >> 2);
            if (k < H)        v = Wih2[row*H + k];
            else if (k < 2*H) v = Whh2[row*H + (k - H)];
        }
        sm[OFF_W2T + idx] = v;
    }
    for (int j = tid; j < GP; j += NT) {
        float wx = 0.f, b1 = 0.f, b2 = 0.f;
        if (j < G4) {
            int row = (j & 3)*H + (j >> 2);
            wx = Wih1[row];
            b1 = bih1[row] + bhh1[row];
            b2 = bih2[row] + bhh2[row];
        }
        sm[OFF_WX + j] = wx;
        sm[OFF_B1 + j] = b1;
        sm[OFF_B2 + j] = b2;
    }
    if (tid < 64) sm[OFF_WL + tid] = (tid < H) ? Wl[tid] : 0.0f;
    for (int idx = tid; idx < SZ_HD; idx += NT) sm[OFF_HD + idx] = 0.0f;
    for (int idx = tid; idx < NKS*SZ_G; idx += NT) sm[OFF_G + idx] = 0.0f;
    if (tid < 8)   sm[OFF_OUT + tid] = 0.0f;
    if (tid == 0)  sm[OFF_BL] = bl[0];
    __syncthreads();

    float c1r[2] = {0.f, 0.f};
    float c2r[2] = {0.f, 0.f};

    const int wid  = tid >> 5, lane = tid & 31;
    const int js   = wid & 1;                // j-slice (2 x 128 cols)
    const int kh   = wid >> 1;               // k-split group (0..3)
    const int j0   = js*128 + lane*4;        // 4 consecutive cols (one unit's gates)
    float* gout = sm + OFF_G + kh*SZ_G;

    // layer1: 26 k-pairs split {7,7,6,6}; layer2: 52 pairs, 13 each
    const int s1 = (kh < 2) ? 7*kh : 14 + 6*(kh - 2);
    const int s2 = 13*kh;
    const float* W1T = sm + OFF_W1T + s1*2*GP;
    const float* W2T = sm + OFF_W2T + s2*2*GP;
    const float* hd1 = sm + OFF_HD + s1*4;
    const float* hd2 = sm + OFF_HD + s2*4;
    float* hd = sm + OFF_HD;

    // x prefetch (kh==0 warps): lane b<8 holds input[(b0+b)*T + t]
    float xcur = 0.f;
    if (kh == 0 && lane < 8) xcur = input[(b0 + lane)*TSEQ];

    for (int t = 0; t < TTOT; ++t) {
        // ---- matvec layer 1 (partial over this warp's k-pairs) ----
        {
            ull acc0[8], acc1[8];
            if (kh == 0) {
                ulonglong2 bv  = *reinterpret_cast<const ulonglong2*>(sm + OFF_B1 + j0);
                ulonglong2 wxv = *reinterpret_cast<const ulonglong2*>(sm + OFF_WX + j0);
                #pragma unroll
                for (int b = 0; b < 8; ++b) {
                    float x = (t < TSEQ) ? __shfl_sync(0xffffffffu, xcur, b)
                                         : sm[OFF_OUT + b];
                    ull xx = dup2(x);
                    acc0[b] = ffma2(wxv.x, xx, bv.x);
                    acc1[b] = ffma2(wxv.y, xx, bv.y);
                }
                if (t + 1 < TSEQ && lane < 8)
                    xcur = input[(b0 + lane)*TSEQ + (t + 1)];
            } else {
                #pragma unroll
                for (int b = 0; b < 8; ++b) { acc0[b] = 0ull; acc1[b] = 0ull; }
            }
            if (kh < 2) matvec<7>(W1T, hd1, acc0, acc1, j0);
            else        matvec<6>(W1T, hd1, acc0, acc1, j0);
            store_acc(gout, acc0, acc1, j0);
        }
        __syncthreads();

        gates(sm + OFF_G, hd, c1r, 0, tid);     // h1 -> hd dup[0..2H)
        __syncthreads();

        // ---- matvec layer 2 (partial over this warp's k-pairs) ----
        {
            ull acc0[8], acc1[8];
            if (kh == 0) {
                ulonglong2 bv = *reinterpret_cast<const ulonglong2*>(sm + OFF_B2 + j0);
                #pragma unroll
                for (int b = 0; b < 8; ++b) { acc0[b] = bv.x; acc1[b] = bv.y; }
            } else {
                #pragma unroll
                for (int b = 0; b < 8; ++b) { acc0[b] = 0ull; acc1[b] = 0ull; }
            }
            matvec<13>(W2T, hd2, acc0, acc1, j0);
            store_acc(gout, acc0, acc1, j0);
        }
        __syncthreads();

        gates(sm + OFF_G, hd, c2r, H, tid);     // h2 -> hd dup[2H..4H)
        __syncthreads();

        // ---- output: out[b] = h2 . Wl + bl ; warp wid handles batch wid ----
        // Reads only h2 (next h2 write is 3 barriers away); needs a trailing
        // barrier only when the NEXT step consumes sm[OFF_OUT] (future phase).
        {
            const float* h2p = hd + wid*HROW + 2*H;
            float p = h2p[2*lane] * sm[OFF_WL + lane];
            if (lane + 32 < H)
                p += h2p[2*(lane + 32)] * sm[OFF_WL + lane + 32];
            #pragma unroll
            for (int o = 16; o > 0; o >>= 1)
                p += __shfl_xor_sync(0xffffffffu, p, o);
            if (lane == 0) {
                float ov = p + sm[OFF_BL];
                out[(b0 + wid)*TTOT + t] = ov;
                sm[OFF_OUT + wid] = ov;   // consumed only when t+1 >= TSEQ
            }
        }
        if (t >= TSEQ - 1) __syncthreads();
    }
}

extern "C" void kernel_launch(void* const* d_in, const int* in_sizes, int n_in,
                              void* d_out, int out_size)
{
    (void)n_in; (void)out_size;
    cudaFuncSetAttribute(lstm_seq_kernel,
                         cudaFuncAttributeMaxDynamicSharedMemorySize, SMEM_BYTES);
    int nblocks = in_sizes[0] / (TSEQ * BB);   // B / 8 = 128
    lstm_seq_kernel<<<nblocks, NT, SMEM_BYTES>>>(
        (const float*)d_in[0],  (const float*)d_in[1], (const float*)d_in[2],
        (const float*)d_in[3],  (const float*)d_in[4], (const float*)d_in[5],
        (const float*)d_in[6],  (const float*)d_in[7], (const float*)d_in[8],
        (const float*)d_in[9],  (const float*)d_in[10],
        (float*)d_out);
}